// round 5
// baseline (speedup 1.0000x reference)
#include <cuda_runtime.h>

// Problem constants
#define B_SZ     32
#define C_INPUT  64
#define L_IN     8192
#define L_OUT    8186
#define PF       128

#define TS       128       // time-tile per CTA (both kernels)
#define THREADS  256

typedef unsigned long long u64;

__device__ __forceinline__ u64 pk2(float lo, float hi) {
    u64 r; asm("mov.b64 %0, {%1, %2};" : "=l"(r) : "f"(lo), "f"(hi)); return r;
}
__device__ __forceinline__ u64 dup2(float v) { return pk2(v, v); }
__device__ __forceinline__ void fma2(u64& d, u64 a, u64 b) {
    asm("fma.rn.f32x2 %0, %1, %2, %0;" : "+l"(d) : "l"(a), "l"(b));
}
__device__ __forceinline__ float2 up2(u64 v) {
    float lo, hi; asm("mov.b64 {%0, %1}, %2;" : "=f"(lo), "=f"(hi) : "l"(v));
    return make_float2(lo, hi);
}

// ---------------- scratch: intermediate feature maps --------------------
// channels 0-5: m7a (valid s in [0,8190))
// channels 6-11: m10b, 12-17: m15b (valid u in [0,8186))
// position p stored at index p+16. Pads [0,16) and tail are NEVER written and
// stay statically zero -> they implement the reference's causal zero-padding.
#define GROW 8448
__device__ float g_mid[B_SZ][18][GROW];

// ======================= KERNEL A: layers 1 + 2 =========================
// SMEM layout (floats)
#define A_XST   136      // x row stride (134 used)
#define A_M1ST  136      // m1 row stride (132 used)
#define A_SX    0
#define A_SM1   (A_SX  + 64 * A_XST)          // 8704
#define A_SW1I  (A_SM1 + 18 * A_M1ST)         // 11152: [9 ocpair][64 c][3 tap][2]
#define A_SW2D  (A_SW1I + 9 * 64 * 6)         // 14608: [12 oc][18 w][2] dup
#define A_FLOATS (A_SW2D + 12 * 36)           // 15040
#define A_BYTES  (A_FLOATS * 4)               // 60160

extern __shared__ float smem[];

__global__ void __launch_bounds__(THREADS, 3) kernelA(
    const float* __restrict__ x,
    const float* __restrict__ w7_1, const float* __restrict__ w10_1,
    const float* __restrict__ w15_1,
    const float* __restrict__ w10_3, const float* __restrict__ w15_3)
{
    float* sx   = smem + A_SX;
    float* sm1  = smem + A_SM1;   // rows: 0-5 m7a, 6-11 m10a, 12-17 m15a
    float* sw1i = smem + A_SW1I;
    float* sw2d = smem + A_SW2D;

    const int tid = threadIdx.x;
    const int b   = blockIdx.y;
    const int s0  = blockIdx.x * TS;

    // stage layer-1 weights, oc-pair interleaved: sw1i[q][c*3+j][s] = w_{2q+s}
    for (int i = tid; i < 18 * 192; i += THREADS) {
        int o = i / 192, r = i % 192;
        float v = (o < 6) ? w7_1[i] : (o < 12) ? w10_1[i - 1152] : w15_1[i - 2304];
        sw1i[((o >> 1) * 192 + r) * 2 + (o & 1)] = v;
    }
    // stage layer-2 weights duplicated
    for (int i = tid; i < 12 * 18; i += THREADS) {
        int o = i / 18, r = i % 18;
        float v = (o < 6) ? w10_3[i] : w15_3[i - 108];
        sw2d[o * 36 + r * 2 + 0] = v;
        sw2d[o * 36 + r * 2 + 1] = v;
    }
    // stage x: 64 channels x 134 positions [s0, s0+134), zero past end
    {
        const float* xb = x + (long long)b * C_INPUT * L_IN;
        int warp = tid >> 5, lane = tid & 31;
        for (int c = warp; c < C_INPUT; c += 8) {
            const float* xc  = xb + (long long)c * L_IN;
            float*       sxc = sx + c * A_XST;
            for (int i = lane; i < 134; i += 32) {
                int g = s0 + i;
                sxc[i] = (g < L_IN) ? xc[g] : 0.0f;
            }
        }
    }
    __syncthreads();

    // ---- layer 1: 9 oc-pairs x 22 six-pos blocks = 198 items (f32x2) ----
    if (tid < 198) {
        int q  = tid / 22;
        int p0 = (tid % 22) * 6;     // positions p0..p0+5 (<=131), x taps to p0+7
        u64 A0=0,A1=0,A2=0,A3=0,A4=0,A5=0;
        const float* wrow = sw1i + q * 384;
        #pragma unroll 2
        for (int c = 0; c < 64; c++) {
            const float* xc = sx + c * A_XST + p0;
            u64 D0=dup2(xc[0]), D1=dup2(xc[1]), D2=dup2(xc[2]), D3=dup2(xc[3]),
                D4=dup2(xc[4]), D5=dup2(xc[5]), D6=dup2(xc[6]), D7=dup2(xc[7]);
            const float* wc = wrow + c * 6;
            u64 W0 = *(const u64*)(wc + 0);
            u64 W1 = *(const u64*)(wc + 2);
            u64 W2 = *(const u64*)(wc + 4);
            fma2(A0,W0,D0); fma2(A0,W1,D1); fma2(A0,W2,D2);
            fma2(A1,W0,D1); fma2(A1,W1,D2); fma2(A1,W2,D3);
            fma2(A2,W0,D2); fma2(A2,W1,D3); fma2(A2,W2,D4);
            fma2(A3,W0,D3); fma2(A3,W1,D4); fma2(A3,W2,D5);
            fma2(A4,W0,D4); fma2(A4,W1,D5); fma2(A4,W2,D6);
            fma2(A5,W0,D5); fma2(A5,W1,D6); fma2(A5,W2,D7);
        }
        float* r0 = sm1 + (2 * q)     * A_M1ST + p0;
        float* r1 = sm1 + (2 * q + 1) * A_M1ST + p0;
        float2 v;
        v=up2(A0); r0[0]=fmaxf(v.x,0.f); r1[0]=fmaxf(v.y,0.f);
        v=up2(A1); r0[1]=fmaxf(v.x,0.f); r1[1]=fmaxf(v.y,0.f);
        v=up2(A2); r0[2]=fmaxf(v.x,0.f); r1[2]=fmaxf(v.y,0.f);
        v=up2(A3); r0[3]=fmaxf(v.x,0.f); r1[3]=fmaxf(v.y,0.f);
        v=up2(A4); r0[4]=fmaxf(v.x,0.f); r1[4]=fmaxf(v.y,0.f);
        v=up2(A5); r0[5]=fmaxf(v.x,0.f); r1[5]=fmaxf(v.y,0.f);
    }
    __syncthreads();

    // ---- phase 2: layer 2 (threads 0-191) + m7a export (all threads) ----
    // layer 2: 12 oc x 16 eight-pos blocks, kw=3 d=2, f32x2
    if (tid < 192) {
        int oc = tid / 16;
        int p0 = (tid % 16) * 8;                   // outputs u0..u0+7
        int br = oc / 6;
        const float* minp = sm1 + (6 + br * 6) * A_M1ST + p0;
        const u64*   wr   = (const u64*)(sw2d + oc * 36);
        u64 A0=0,A1=0,A2=0,A3=0;
        #pragma unroll
        for (int c = 0; c < 6; c++) {
            const float* mc = minp + c * A_M1ST;
            u64 D0=*(const u64*)(mc+0),  D1=*(const u64*)(mc+2),
                D2=*(const u64*)(mc+4),  D3=*(const u64*)(mc+6),
                D4=*(const u64*)(mc+8),  D5=*(const u64*)(mc+10);
            u64 W0=wr[c*3+0], W1=wr[c*3+1], W2=wr[c*3+2];
            fma2(A0,W0,D0); fma2(A0,W1,D1); fma2(A0,W2,D2);
            fma2(A1,W0,D1); fma2(A1,W1,D2); fma2(A1,W2,D3);
            fma2(A2,W0,D2); fma2(A2,W1,D3); fma2(A2,W2,D4);
            fma2(A3,W0,D3); fma2(A3,W1,D4); fma2(A3,W2,D5);
        }
        float* gr = &g_mid[b][6 + oc][0];
        u64 accs[4] = {A0, A1, A2, A3};
        #pragma unroll
        for (int k = 0; k < 4; k++) {
            int u = s0 + p0 + 2 * k;
            float2 v = up2(accs[k]);
            v.x = fmaxf(v.x, 0.f); v.y = fmaxf(v.y, 0.f);
            if (u + 1 < 8186)      *(float2*)(gr + u + 16) = v;
            else if (u < 8186)     gr[u + 16] = v.x;
        }
    }
    // m7a export: 6 ch x 32 four-pos blocks = 192 items
    for (int idx = tid; idx < 192; idx += THREADS) {
        int ch = idx / 32, p0 = (idx % 32) * 4;
        int s  = s0 + p0;
        float4 v = *(const float4*)(sm1 + ch * A_M1ST + p0);  // already relu'd
        float* gr = &g_mid[b][ch][s + 16];
        if (s + 3 < 8190) {
            *(float4*)gr = v;
        } else {
            if (s     < 8190) gr[0] = v.x;
            if (s + 1 < 8190) gr[1] = v.y;
            if (s + 2 < 8190) gr[2] = v.z;
            if (s + 3 < 8190) gr[3] = v.w;
        }
    }
}

// ======================= KERNEL B: final layer ==========================
// SMEM layout (floats)
#define B_ST    140      // s18 row stride (140 used)
#define B_S18   0
#define B_SW7D  (B_S18  + 18 * B_ST)     // 2520:  [128][18][2] dup
#define B_SW10D (B_SW7D + 128 * 36)      // 7128:  [128][12][2] dup
#define B_SW15D (B_SW10D + 128 * 24)     // 10200: [128][18][2] dup
#define B_FLOATS (B_SW15D + 128 * 36)    // 14808
#define B_BYTES  (B_FLOATS * 4)          // 59232

__device__ __forceinline__ void storep4(float* outb, int o, int t, u64 A01, u64 A23)
{
    float2 v0 = up2(A01), v1 = up2(A23);
    v0.x = fmaxf(v0.x, 0.f); v0.y = fmaxf(v0.y, 0.f);
    v1.x = fmaxf(v1.x, 0.f); v1.y = fmaxf(v1.y, 0.f);
    float* op = outb + (long long)o * L_OUT + t;
    if (t + 3 < L_OUT) {
        __stcs((float2*)op,       v0);
        __stcs((float2*)(op + 2), v1);
    } else {
        if (t     < L_OUT) op[0] = v0.x;
        if (t + 1 < L_OUT) op[1] = v0.y;
        if (t + 2 < L_OUT) op[2] = v1.x;
        if (t + 3 < L_OUT) op[3] = v1.y;
    }
}

__global__ void __launch_bounds__(THREADS, 3) kernelB(
    const float* __restrict__ w7_3, const float* __restrict__ w10_5,
    const float* __restrict__ w15_5,
    float* __restrict__ out)
{
    float* s18   = smem + B_S18;    // [18][140], local j <-> global t0-8+j
    float* sw7d  = smem + B_SW7D;
    float* sw10d = smem + B_SW10D;
    float* sw15d = smem + B_SW15D;

    const int tid = threadIdx.x;
    const int b   = blockIdx.y;
    const int t0  = blockIdx.x * TS;

    // stage weights (duplicated pairs)
    for (int i = tid; i < 128 * 18; i += THREADS) {
        int o = i / 18, r = i % 18;
        float v7 = w7_3[i], v15 = w15_5[i];
        sw7d [o * 36 + r * 2 + 0] = v7;  sw7d [o * 36 + r * 2 + 1] = v7;
        sw15d[o * 36 + r * 2 + 0] = v15; sw15d[o * 36 + r * 2 + 1] = v15;
    }
    for (int i = tid; i < 128 * 12; i += THREADS) {
        int o = i / 12, r = i % 12;
        float v = w10_5[i];
        sw10d[o * 24 + r * 2 + 0] = v;
        sw10d[o * 24 + r * 2 + 1] = v;
    }
    // stage 18 channels x 140 positions from scratch (pads supply causal zeros)
    for (int i = tid; i < 18 * 140; i += THREADS) {
        int ch = i / 140, j = i % 140;
        s18[ch * B_ST + j] = g_mid[b][ch][t0 + 8 + j];
    }
    __syncthreads();

    const int g    = tid >> 5;
    const int lane = tid & 31;
    const int p0   = lane * 4;
    const int t    = t0 + p0;
    float* outb = out + (long long)b * (3 * PF) * L_OUT;

    // ----- branch 7: rows 0-5, values t..t+7 -> pairs at local p0+8+2j -----
    {
        u64 P[6][4];
        #pragma unroll
        for (int c = 0; c < 6; c++) {
            const float* mc = s18 + c * B_ST + p0 + 8;
            P[c][0]=*(const u64*)(mc+0); P[c][1]=*(const u64*)(mc+2);
            P[c][2]=*(const u64*)(mc+4); P[c][3]=*(const u64*)(mc+6);
        }
        #pragma unroll 2
        for (int k = 0; k < 16; k++) {
            int o = g * 16 + k;
            const ulonglong2* q = (const ulonglong2*)(sw7d + o * 36);
            u64 A01 = 0, A23 = 0;
            #pragma unroll
            for (int c = 0; c < 6; c++) {
                // weights r = c*3+j as dup u64s, fetched as LDS.128 pairs
                u64 W0 = ((const u64*)q)[c*3+0];
                u64 W1 = ((const u64*)q)[c*3+1];
                u64 W2 = ((const u64*)q)[c*3+2];
                fma2(A01,W0,P[c][0]); fma2(A01,W1,P[c][1]); fma2(A01,W2,P[c][2]);
                fma2(A23,W0,P[c][1]); fma2(A23,W1,P[c][2]); fma2(A23,W2,P[c][3]);
            }
            storep4(outb, o, t, A01, A23);
        }
    }

    // ----- branch 10: rows 6-11, values t-4..t+3 -> pairs at local p0+4+2j -----
    {
        u64 P[6][4];
        #pragma unroll
        for (int c = 0; c < 6; c++) {
            const float* mc = s18 + (6 + c) * B_ST + p0 + 4;
            P[c][0]=*(const u64*)(mc+0); P[c][1]=*(const u64*)(mc+2);
            P[c][2]=*(const u64*)(mc+4); P[c][3]=*(const u64*)(mc+6);
        }
        #pragma unroll 2
        for (int k = 0; k < 16; k++) {
            int o = g * 16 + k;
            const u64* q = (const u64*)(sw10d + o * 24);
            u64 A01 = 0, A23 = 0;
            #pragma unroll
            for (int c = 0; c < 6; c++) {
                u64 W0 = q[c*2+0], W1 = q[c*2+1];
                fma2(A01,W0,P[c][0]); fma2(A01,W1,P[c][2]);
                fma2(A23,W0,P[c][1]); fma2(A23,W1,P[c][3]);
            }
            storep4(outb, 128 + o, t, A01, A23);
        }
    }

    // ----- branch 15: rows 12-17, two 2-position passes (reg slim) -----
    #pragma unroll
    for (int r = 0; r < 2; r++) {
        u64 P[6][3];
        #pragma unroll
        for (int c = 0; c < 6; c++) {
            const float* mc = s18 + (12 + c) * B_ST + p0 + 2 * r;
            P[c][0]=*(const u64*)(mc+0);
            P[c][1]=*(const u64*)(mc+4);
            P[c][2]=*(const u64*)(mc+8);
        }
        #pragma unroll 2
        for (int k = 0; k < 16; k++) {
            int o = g * 16 + k;
            const u64* q = (const u64*)(sw15d + o * 36);
            u64 A = 0;
            #pragma unroll
            for (int c = 0; c < 6; c++) {
                fma2(A, q[c*3+0], P[c][0]);
                fma2(A, q[c*3+1], P[c][1]);
                fma2(A, q[c*3+2], P[c][2]);
            }
            float2 v = up2(A);
            v.x = fmaxf(v.x, 0.f); v.y = fmaxf(v.y, 0.f);
            int tt = t + 2 * r;
            float* op = outb + (long long)(256 + o) * L_OUT + tt;
            if (tt + 1 < L_OUT)      __stcs((float2*)op, v);
            else if (tt < L_OUT)     op[0] = v.x;
        }
    }
}

// ============================== launch ==================================
extern "C" void kernel_launch(void* const* d_in, const int* in_sizes, int n_in,
                              void* d_out, int out_size)
{
    const float* x     = (const float*)d_in[0];
    const float* w7_1  = (const float*)d_in[1];
    const float* w7_3  = (const float*)d_in[2];
    const float* w10_1 = (const float*)d_in[3];
    const float* w10_3 = (const float*)d_in[4];
    const float* w10_5 = (const float*)d_in[5];
    const float* w15_1 = (const float*)d_in[6];
    const float* w15_3 = (const float*)d_in[7];
    const float* w15_5 = (const float*)d_in[8];
    float* out = (float*)d_out;

    static bool attr_done = false;
    if (!attr_done) {
        cudaFuncSetAttribute(kernelA, cudaFuncAttributeMaxDynamicSharedMemorySize, A_BYTES);
        cudaFuncSetAttribute(kernelB, cudaFuncAttributeMaxDynamicSharedMemorySize, B_BYTES);
        attr_done = true;
    }

    dim3 grid(64, B_SZ);
    kernelA<<<grid, THREADS, A_BYTES>>>(x, w7_1, w10_1, w15_1, w10_3, w15_3);
    kernelB<<<grid, THREADS, B_BYTES>>>(w7_3, w10_5, w15_5, out);
}

// round 6
// speedup vs baseline: 1.0049x; 1.0049x over previous
#include <cuda_runtime.h>

// Problem constants
#define B_SZ     32
#define C_INPUT  64
#define L_IN     8192
#define L_OUT    8186
#define PF       128

#define TS       128       // time-tile per CTA (both kernels)
#define THREADS  256

typedef unsigned long long u64;

__device__ __forceinline__ u64 pk2(float lo, float hi) {
    u64 r; asm("mov.b64 %0, {%1, %2};" : "=l"(r) : "f"(lo), "f"(hi)); return r;
}
__device__ __forceinline__ u64 dup2(float v) { return pk2(v, v); }
__device__ __forceinline__ void fma2(u64& d, u64 a, u64 b) {
    asm("fma.rn.f32x2 %0, %1, %2, %0;" : "+l"(d) : "l"(a), "l"(b));
}
__device__ __forceinline__ float2 up2(u64 v) {
    float lo, hi; asm("mov.b64 {%0, %1}, %2;" : "=f"(lo), "=f"(hi) : "l"(v));
    return make_float2(lo, hi);
}

// ---------------- scratch: intermediate feature maps --------------------
// channels 0-5: m7a (valid s in [0,8190))
// channels 6-11: m10b, 12-17: m15b (valid u in [0,8186))
// position p stored at index p+16. Pads [0,16) and tail are NEVER written and
// stay statically zero -> they implement the reference's causal zero-padding.
#define GROW 8448
__device__ float g_mid[B_SZ][18][GROW];

extern __shared__ float smem[];

// ======================= KERNEL A: layers 1 + 2 =========================
// SMEM layout (floats)
#define A_XST   140      // x row stride (134 real + zero pad to 140)
#define A_M1ST  136      // m1 row stride (135 used)
#define A_SX    0
#define A_SM1   (A_SX  + 64 * A_XST)          // 8960
#define A_SW1   (A_SM1 + 18 * A_M1ST)         // 11408: [9 ocpair][64 c][8] (6 used)
#define A_SW2   (A_SW1 + 9 * 64 * 8)          // 16016: [12 oc][6 c][8] dup (6 used)
#define A_FLOATS (A_SW2 + 12 * 6 * 8)         // 16592
#define A_BYTES  (A_FLOATS * 4)               // 66368 -> 3 CTAs/SM

__global__ void __launch_bounds__(THREADS, 3) kernelA(
    const float* __restrict__ x,
    const float* __restrict__ w7_1, const float* __restrict__ w10_1,
    const float* __restrict__ w15_1,
    const float* __restrict__ w10_3, const float* __restrict__ w15_3)
{
    float* sx  = smem + A_SX;
    float* sm1 = smem + A_SM1;   // rows: 0-5 m7a, 6-11 m10a, 12-17 m15a
    float* sw1 = smem + A_SW1;
    float* sw2 = smem + A_SW2;

    const int tid = threadIdx.x;
    const int b   = blockIdx.y;
    const int s0  = blockIdx.x * TS;

    // stage layer-1 weights: sw1[(q*64+c)*8 + j*2 + s] = w_{2q+s}[c*3+j]
    for (int i = tid; i < 18 * 192; i += THREADS) {
        int o = i / 192, r = i % 192, c = r / 3, j = r % 3;
        float v = (o < 6) ? w7_1[i] : (o < 12) ? w10_1[i - 1152] : w15_1[i - 2304];
        sw1[(((o >> 1) * 64 + c) * 8) + j * 2 + (o & 1)] = v;
    }
    // stage layer-2 weights duplicated: sw2[(oc*6+c)*8 + j*2 + {0,1}]
    for (int i = tid; i < 12 * 18; i += THREADS) {
        int o = i / 18, r = i % 18, c = r / 3, j = r % 3;
        float v = (o < 6) ? w10_3[i] : w15_3[i - 108];
        int base = (o * 6 + c) * 8 + j * 2;
        sw2[base] = v; sw2[base + 1] = v;
    }
    // stage x: 64 ch x 134 real positions [s0, s0+134), zero-pad to 140
    {
        const float* xb = x + (long long)b * C_INPUT * L_IN;
        int warp = tid >> 5, lane = tid & 31;
        for (int c = warp; c < C_INPUT; c += 8) {
            const float* xc  = xb + (long long)c * L_IN;
            float*       sxc = sx + c * A_XST;
            for (int i = lane; i < A_XST; i += 32) {
                int g = s0 + i;
                sxc[i] = (i < 134 && g < L_IN) ? xc[g] : 0.0f;
            }
        }
    }
    __syncthreads();

    // ---- layer 1: 9 oc-pairs x 27 five-pos blocks = 243 items (f32x2) ----
    if (tid < 243) {
        int q  = tid / 27;
        int p0 = (tid % 27) * 5;        // outputs p0..p0+4, x taps to p0+6
        u64 A0 = 0, A1 = 0, A2 = 0, A3 = 0, A4 = 0;
        const float* wrow = sw1 + q * 512;
        #pragma unroll 1
        for (int c = 0; c < 64; c++) {
            const float* xc = sx + c * A_XST + p0;
            u64 D0 = dup2(xc[0]), D1 = dup2(xc[1]), D2 = dup2(xc[2]),
                D3 = dup2(xc[3]), D4 = dup2(xc[4]), D5 = dup2(xc[5]),
                D6 = dup2(xc[6]);
            const float* wc = wrow + c * 8;
            ulonglong2 w01 = *(const ulonglong2*)wc;     // (W0, W1)
            u64 W2 = *(const u64*)(wc + 4);
            fma2(A0, w01.x, D0); fma2(A0, w01.y, D1); fma2(A0, W2, D2);
            fma2(A1, w01.x, D1); fma2(A1, w01.y, D2); fma2(A1, W2, D3);
            fma2(A2, w01.x, D2); fma2(A2, w01.y, D3); fma2(A2, W2, D4);
            fma2(A3, w01.x, D3); fma2(A3, w01.y, D4); fma2(A3, W2, D5);
            fma2(A4, w01.x, D4); fma2(A4, w01.y, D5); fma2(A4, W2, D6);
        }
        float* r0 = sm1 + (2 * q)     * A_M1ST + p0;
        float* r1 = sm1 + (2 * q + 1) * A_M1ST + p0;
        float2 v;
        v = up2(A0); r0[0] = fmaxf(v.x, 0.f); r1[0] = fmaxf(v.y, 0.f);
        v = up2(A1); r0[1] = fmaxf(v.x, 0.f); r1[1] = fmaxf(v.y, 0.f);
        v = up2(A2); r0[2] = fmaxf(v.x, 0.f); r1[2] = fmaxf(v.y, 0.f);
        v = up2(A3); r0[3] = fmaxf(v.x, 0.f); r1[3] = fmaxf(v.y, 0.f);
        v = up2(A4); r0[4] = fmaxf(v.x, 0.f); r1[4] = fmaxf(v.y, 0.f);
    }
    __syncthreads();

    // ---- phase 2: layer 2 (threads 0-191) + m7a export (all threads) ----
    if (tid < 192) {
        int oc = tid / 16;
        int p0 = (tid % 16) * 8;                   // outputs u0..u0+7
        int br = oc / 6;
        const float* minp = sm1 + (6 + br * 6) * A_M1ST + p0;
        const float* wrow = sw2 + oc * 48;
        u64 A0 = 0, A1 = 0, A2 = 0, A3 = 0;
        #pragma unroll
        for (int c = 0; c < 6; c++) {
            const float* mc = minp + c * A_M1ST;
            ulonglong2 d01 = *(const ulonglong2*)(mc + 0);   // (D0,D1)
            ulonglong2 d23 = *(const ulonglong2*)(mc + 4);   // (D2,D3)
            ulonglong2 d45 = *(const ulonglong2*)(mc + 8);   // (D4,D5)
            const float* wc = wrow + c * 8;
            ulonglong2 w01 = *(const ulonglong2*)wc;
            u64 W2 = *(const u64*)(wc + 4);
            fma2(A0, w01.x, d01.x); fma2(A0, w01.y, d01.y); fma2(A0, W2, d23.x);
            fma2(A1, w01.x, d01.y); fma2(A1, w01.y, d23.x); fma2(A1, W2, d23.y);
            fma2(A2, w01.x, d23.x); fma2(A2, w01.y, d23.y); fma2(A2, W2, d45.x);
            fma2(A3, w01.x, d23.y); fma2(A3, w01.y, d45.x); fma2(A3, W2, d45.y);
        }
        float* gr = &g_mid[b][6 + oc][0];
        u64 accs[4] = {A0, A1, A2, A3};
        #pragma unroll
        for (int k = 0; k < 4; k++) {
            int u = s0 + p0 + 2 * k;
            float2 v = up2(accs[k]);
            v.x = fmaxf(v.x, 0.f); v.y = fmaxf(v.y, 0.f);
            if (u + 1 < 8186)      *(float2*)(gr + u + 16) = v;
            else if (u < 8186)     gr[u + 16] = v.x;
        }
    }
    // m7a export: 6 ch x 32 four-pos blocks = 192 items
    for (int idx = tid; idx < 192; idx += THREADS) {
        int ch = idx / 32, p0 = (idx % 32) * 4;
        int s  = s0 + p0;
        float4 v = *(const float4*)(sm1 + ch * A_M1ST + p0);  // already relu'd
        float* gr = &g_mid[b][ch][s + 16];
        if (s + 3 < 8190) {
            *(float4*)gr = v;
        } else {
            if (s     < 8190) gr[0] = v.x;
            if (s + 1 < 8190) gr[1] = v.y;
            if (s + 2 < 8190) gr[2] = v.z;
            if (s + 3 < 8190) gr[3] = v.w;
        }
    }
}

// ======================= KERNEL B: final layer ==========================
// SMEM layout (floats)
#define B_ST    140
#define B_S18   0
#define B_SW7   (B_S18 + 18 * B_ST)       // 2520:  [128][6][8] dup (6 used)
#define B_SW10  (B_SW7 + 128 * 48)        // 8664:  [128][6][4] dup
#define B_SW15  (B_SW10 + 128 * 24)       // 11736: [128][6][8] dup
#define B_FLOATS (B_SW15 + 128 * 48)      // 17880
#define B_BYTES  (B_FLOATS * 4)           // 71520 -> 3 CTAs/SM

__device__ __forceinline__ void storep4(float* outb, int o, int t, u64 A01, u64 A23)
{
    float2 v0 = up2(A01), v1 = up2(A23);
    v0.x = fmaxf(v0.x, 0.f); v0.y = fmaxf(v0.y, 0.f);
    v1.x = fmaxf(v1.x, 0.f); v1.y = fmaxf(v1.y, 0.f);
    float* op = outb + (long long)o * L_OUT + t;
    if (t + 3 < L_OUT) {
        __stcs((float2*)op,       v0);
        __stcs((float2*)(op + 2), v1);
    } else {
        if (t     < L_OUT) op[0] = v0.x;
        if (t + 1 < L_OUT) op[1] = v0.y;
        if (t + 2 < L_OUT) op[2] = v1.x;
        if (t + 3 < L_OUT) op[3] = v1.y;
    }
}

__global__ void __launch_bounds__(THREADS, 3) kernelB(
    const float* __restrict__ w7_3, const float* __restrict__ w10_5,
    const float* __restrict__ w15_5,
    float* __restrict__ out)
{
    float* s18  = smem + B_S18;    // [18][140], local j <-> global t0-8+j
    float* sw7  = smem + B_SW7;
    float* sw10 = smem + B_SW10;
    float* sw15 = smem + B_SW15;

    const int tid = threadIdx.x;
    const int b   = blockIdx.y;
    const int t0  = blockIdx.x * TS;

    // stage weights (dup pairs, rows padded for LDS.128)
    for (int i = tid; i < 128 * 18; i += THREADS) {
        int o = i / 18, r = i % 18, c = r / 3, j = r % 3;
        int base = (o * 6 + c) * 8 + j * 2;
        float v7 = w7_3[i], v15 = w15_5[i];
        sw7 [base] = v7;  sw7 [base + 1] = v7;
        sw15[base] = v15; sw15[base + 1] = v15;
    }
    for (int i = tid; i < 128 * 12; i += THREADS) {
        int o = i / 12, r = i % 12, c = r / 2, j = r % 2;
        int base = (o * 6 + c) * 4 + j * 2;
        float v = w10_5[i];
        sw10[base] = v; sw10[base + 1] = v;
    }
    // stage 18 channels x 140 positions from scratch (pads supply causal zeros)
    for (int i = tid; i < 18 * 140; i += THREADS) {
        int ch = i / 140, j = i % 140;
        s18[ch * B_ST + j] = g_mid[b][ch][t0 + 8 + j];
    }
    __syncthreads();

    const int g    = tid >> 5;
    const int lane = tid & 31;
    const int p0   = lane * 4;
    const int t    = t0 + p0;
    float* outb = out + (long long)b * (3 * PF) * L_OUT;

    // ----- branch 7: rows 0-5, pairs at local p0+8+2j -----
    {
        u64 P[6][4];
        #pragma unroll
        for (int c = 0; c < 6; c++) {
            const ulonglong2* mc = (const ulonglong2*)(s18 + c * B_ST + p0 + 8);
            ulonglong2 lo = mc[0], hi = mc[1];
            P[c][0] = lo.x; P[c][1] = lo.y; P[c][2] = hi.x; P[c][3] = hi.y;
        }
        #pragma unroll 2
        for (int k = 0; k < 16; k++) {
            int o = g * 16 + k;
            const float* wrow = sw7 + o * 48;
            u64 A01 = 0, A23 = 0;
            #pragma unroll
            for (int c = 0; c < 6; c++) {
                const float* wc = wrow + c * 8;
                ulonglong2 w01 = *(const ulonglong2*)wc;
                u64 W2 = *(const u64*)(wc + 4);
                fma2(A01, w01.x, P[c][0]); fma2(A01, w01.y, P[c][1]); fma2(A01, W2, P[c][2]);
                fma2(A23, w01.x, P[c][1]); fma2(A23, w01.y, P[c][2]); fma2(A23, W2, P[c][3]);
            }
            storep4(outb, o, t, A01, A23);
        }
    }

    // ----- branch 10: rows 6-11, pairs at local p0+4+4j -----
    {
        u64 P[6][4];
        #pragma unroll
        for (int c = 0; c < 6; c++) {
            const ulonglong2* mc = (const ulonglong2*)(s18 + (6 + c) * B_ST + p0 + 4);
            ulonglong2 lo = mc[0], hi = mc[1];
            P[c][0] = lo.x; P[c][1] = lo.y; P[c][2] = hi.x; P[c][3] = hi.y;
        }
        #pragma unroll 2
        for (int k = 0; k < 16; k++) {
            int o = g * 16 + k;
            const float* wrow = sw10 + o * 24;
            u64 A01 = 0, A23 = 0;
            #pragma unroll
            for (int c = 0; c < 6; c++) {
                ulonglong2 w01 = *(const ulonglong2*)(wrow + c * 4);
                fma2(A01, w01.x, P[c][0]); fma2(A01, w01.y, P[c][2]);
                fma2(A23, w01.x, P[c][1]); fma2(A23, w01.y, P[c][3]);
            }
            storep4(outb, 128 + o, t, A01, A23);
        }
    }

    // ----- branch 15: rows 12-17, two 2-position passes, taps at p0+2r+4j -----
    #pragma unroll
    for (int r = 0; r < 2; r++) {
        u64 P[6][3];
        #pragma unroll
        for (int c = 0; c < 6; c++) {
            const float* mc = s18 + (12 + c) * B_ST + p0 + 2 * r;
            P[c][0] = *(const u64*)(mc + 0);
            P[c][1] = *(const u64*)(mc + 4);
            P[c][2] = *(const u64*)(mc + 8);
        }
        #pragma unroll 2
        for (int k = 0; k < 16; k++) {
            int o = g * 16 + k;
            const float* wrow = sw15 + o * 48;
            u64 A = 0;
            #pragma unroll
            for (int c = 0; c < 6; c++) {
                const float* wc = wrow + c * 8;
                ulonglong2 w01 = *(const ulonglong2*)wc;
                u64 W2 = *(const u64*)(wc + 4);
                fma2(A, w01.x, P[c][0]);
                fma2(A, w01.y, P[c][1]);
                fma2(A, W2,    P[c][2]);
            }
            float2 v = up2(A);
            v.x = fmaxf(v.x, 0.f); v.y = fmaxf(v.y, 0.f);
            int tt = t + 2 * r;
            float* op = outb + (long long)(256 + o) * L_OUT + tt;
            if (tt + 1 < L_OUT)      __stcs((float2*)op, v);
            else if (tt < L_OUT)     op[0] = v.x;
        }
    }
}

// ============================== launch ==================================
extern "C" void kernel_launch(void* const* d_in, const int* in_sizes, int n_in,
                              void* d_out, int out_size)
{
    const float* x     = (const float*)d_in[0];
    const float* w7_1  = (const float*)d_in[1];
    const float* w7_3  = (const float*)d_in[2];
    const float* w10_1 = (const float*)d_in[3];
    const float* w10_3 = (const float*)d_in[4];
    const float* w10_5 = (const float*)d_in[5];
    const float* w15_1 = (const float*)d_in[6];
    const float* w15_3 = (const float*)d_in[7];
    const float* w15_5 = (const float*)d_in[8];
    float* out = (float*)d_out;

    static bool attr_done = false;
    if (!attr_done) {
        cudaFuncSetAttribute(kernelA, cudaFuncAttributeMaxDynamicSharedMemorySize, A_BYTES);
        cudaFuncSetAttribute(kernelB, cudaFuncAttributeMaxDynamicSharedMemorySize, B_BYTES);
        attr_done = true;
    }

    dim3 grid(64, B_SZ);
    kernelA<<<grid, THREADS, A_BYTES>>>(x, w7_1, w10_1, w15_1, w10_3, w15_3);
    kernelB<<<grid, THREADS, B_BYTES>>>(w7_3, w10_5, w15_5, out);
}